// round 1
// baseline (speedup 1.0000x reference)
#include <cuda_runtime.h>
#include <cuda_bf16.h>
#include <math.h>

// ---------------------------------------------------------------------------
// RPNClassificationLoss
//   K1: per-proposal max IoU over all GT boxes (division-free argmax via
//       FMA-compensated cross-multiplication; one IEEE div at the end).
//   K2: per-chunk bitonic sort -> top-128 / bottom-128 candidates per chunk.
//   K3: single-block merge sort of candidates -> exact global top/bottom 128
//       with jax top_k tie semantics -> BCE mean.
// ---------------------------------------------------------------------------

#define GT_TILE 512
#define CH 4096           // chunk size for block-level selection (power of 2)
#define MAX_N 131072      // max proposals supported (actual n = 100000)
#define MAX_CAND 4096     // >= ceil(MAX_N/CH)*128

__device__ unsigned long long g_keys[MAX_N];
__device__ unsigned long long g_candT[MAX_CAND];
__device__ unsigned long long g_candB[MAX_CAND];

// ---------------------------------------------------------------------------
// K1: IoU + rowmax.  keyB[i] = (float_bits(max_iou_i) << 32) | i
// ---------------------------------------------------------------------------
__global__ void __launch_bounds__(256) iou_rowmax_kernel(
    const float4* __restrict__ props, const float4* __restrict__ gts,
    int n, int g)
{
    __shared__ float4 s_box[GT_TILE];
    __shared__ float  s_area[GT_TILE];

    int i = blockIdx.x * blockDim.x + threadIdx.x;
    float4 p = make_float4(0.f, 0.f, 0.f, 0.f);
    float areaP = 0.f;
    if (i < n) {
        p = props[i];
        areaP = (p.z - p.x) * (p.w - p.y);
    }

    float bestI = 0.f;   // running best (inter, union); value = bestI/bestU
    float bestU = 1.f;

    for (int t0 = 0; t0 < g; t0 += GT_TILE) {
        int cnt = min(GT_TILE, g - t0);
        __syncthreads();
        for (int j = threadIdx.x; j < cnt; j += blockDim.x) {
            float4 b = gts[t0 + j];
            s_box[j]  = b;
            s_area[j] = (b.z - b.x) * (b.w - b.y);
        }
        __syncthreads();
        if (i < n) {
            #pragma unroll 4
            for (int j = 0; j < cnt; j++) {
                float4 b = s_box[j];
                float  ga = s_area[j];
                float lx = fmaxf(p.x, b.x);
                float ly = fmaxf(p.y, b.y);
                float rx = fminf(p.z, b.z);
                float ry = fminf(p.w, b.w);
                float w  = fmaxf(rx - lx, 0.f);
                float h  = fmaxf(ry - ly, 0.f);
                float inter = w * h;
                float uni   = (ga + areaP) - inter;   // same op order as reference
                // exact compare inter/uni > bestI/bestU  (positive denominators)
                float s1 = inter * bestU;
                float s2 = bestI * uni;
                float e1 = fmaf(inter, bestU, -s1);
                float e2 = fmaf(bestI, uni,  -s2);
                bool better = (s1 > s2) || ((s1 == s2) && (e1 > e2));
                if (better) { bestI = inter; bestU = uni; }
            }
        }
    }

    if (i < n) {
        float v = __fdiv_rn(bestI, bestU);           // correctly rounded, like ref
        unsigned int vb = __float_as_uint(v);        // v >= 0 -> monotone bits
        g_keys[i] = ((unsigned long long)vb << 32) | (unsigned int)i;
    }
}

// ---------------------------------------------------------------------------
// shared-memory bitonic sort (ascending), CH elements, all threads participate
// ---------------------------------------------------------------------------
__device__ __forceinline__ void bitonic_sort_sh(unsigned long long* s)
{
    for (int k = 2; k <= CH; k <<= 1) {
        for (int j = k >> 1; j > 0; j >>= 1) {
            for (int i = threadIdx.x; i < CH; i += blockDim.x) {
                int ixj = i ^ j;
                if (ixj > i) {
                    unsigned long long a = s[i];
                    unsigned long long b = s[ixj];
                    bool up = ((i & k) == 0);
                    if ((a > b) == up) { s[i] = b; s[ixj] = a; }
                }
            }
            __syncthreads();
        }
    }
}

// ---------------------------------------------------------------------------
// K2: per-chunk selection.
//   keyB = (val<<32)|i     : ascending sort -> first 128 = bottom candidates
//   keyT = keyB ^ 0xFFFFFFFF (= (val<<32)|~i): ascending sort -> last 128 = top
// ---------------------------------------------------------------------------
__global__ void __launch_bounds__(512) chunk_select_kernel(int n)
{
    __shared__ unsigned long long s[CH];
    int base = blockIdx.x * CH;

    for (int j = threadIdx.x; j < CH; j += blockDim.x) {
        int gi = base + j;
        s[j] = (gi < n) ? g_keys[gi] : 0xFFFFFFFFFFFFFFFFull;   // pads to the end
    }
    __syncthreads();

    bitonic_sort_sh(s);                                         // ascending keyB

    for (int j = threadIdx.x; j < 128; j += blockDim.x)
        g_candB[blockIdx.x * 128 + j] = s[j];
    __syncthreads();

    // transform in place to keyT; pads (high word > bits(1.0f)) become 0
    for (int j = threadIdx.x; j < CH; j += blockDim.x) {
        unsigned long long k = s[j];
        s[j] = ((unsigned int)(k >> 32) > 0x3F800000u) ? 0ull
                                                       : (k ^ 0xFFFFFFFFull);
    }
    __syncthreads();

    bitonic_sort_sh(s);                                         // ascending keyT

    for (int j = threadIdx.x; j < 128; j += blockDim.x)
        g_candT[blockIdx.x * 128 + j] = s[CH - 128 + j];
}

// ---------------------------------------------------------------------------
// K3: merge candidates, pick exact global 128+128, compute BCE mean.
// ---------------------------------------------------------------------------
__global__ void __launch_bounds__(512) final_loss_kernel(
    int nc, const float* __restrict__ obj, float* __restrict__ out)
{
    __shared__ unsigned long long s[CH];
    __shared__ float red[512];

    float sum = 0.f;

    // ---- top 128 (keyT order: val desc, then lower index first) ----
    for (int j = threadIdx.x; j < CH; j += blockDim.x)
        s[j] = (j < nc) ? g_candT[j] : 0ull;                    // pads to front
    __syncthreads();
    bitonic_sort_sh(s);
    if (threadIdx.x < 128) {
        unsigned long long k = s[CH - 128 + threadIdx.x];
        float v = __uint_as_float((unsigned int)(k >> 32));
        unsigned int idx = 0xFFFFFFFFu - (unsigned int)(k & 0xFFFFFFFFull);
        float o = obj[idx];
        float pcl = fminf(fmaxf(o, 1e-7f), 1.0f - 1e-7f);
        // label = (pos_iou > 0.5)
        sum += (v > 0.5f) ? logf(pcl) : log1pf(-pcl);
    }
    __syncthreads();

    // ---- bottom 128 (keyB order: val asc, then lower index first) ----
    for (int j = threadIdx.x; j < CH; j += blockDim.x)
        s[j] = (j < nc) ? g_candB[j] : 0xFFFFFFFFFFFFFFFFull;   // pads to back
    __syncthreads();
    bitonic_sort_sh(s);
    if (threadIdx.x < 128) {
        unsigned long long k = s[threadIdx.x];
        unsigned int idx = (unsigned int)(k & 0xFFFFFFFFull);
        float o = obj[idx];
        float pcl = fminf(fmaxf(o, 1e-7f), 1.0f - 1e-7f);
        sum += log1pf(-pcl);                                    // label = 0
    }

    // ---- block reduction ----
    red[threadIdx.x] = sum;
    __syncthreads();
    for (int st = 256; st > 0; st >>= 1) {
        if (threadIdx.x < st) red[threadIdx.x] += red[threadIdx.x + st];
        __syncthreads();
    }
    if (threadIdx.x == 0) out[0] = -red[0] / 256.0f;
}

// ---------------------------------------------------------------------------
extern "C" void kernel_launch(void* const* d_in, const int* in_sizes, int n_in,
                              void* d_out, int out_size)
{
    const float*  obj   = (const float*) d_in[0];
    const float4* props = (const float4*)d_in[1];
    const float4* gts   = (const float4*)d_in[2];
    int n = in_sizes[0];           // 100000
    int g = in_sizes[2] / 4;       // 512

    int nb1 = (n + 255) / 256;
    iou_rowmax_kernel<<<nb1, 256>>>(props, gts, n, g);

    int nb2 = (n + CH - 1) / CH;   // 25 chunks
    chunk_select_kernel<<<nb2, 512>>>(n);

    final_loss_kernel<<<1, 512>>>(nb2 * 128, obj, (float*)d_out);
}

// round 3
// speedup vs baseline: 2.0803x; 2.0803x over previous
#include <cuda_runtime.h>
#include <cuda_bf16.h>
#include <math.h>

// ---------------------------------------------------------------------------
// RPNClassificationLoss
//   K1: per-proposal max IoU over all GT (division-free rational argmax,
//       one IEEE division per proposal at the end). 2 proposals/thread.
//   K2: per-chunk exact top-128 / bottom-128 via register-resident warp
//       bitonic sort + merge-keep-128 (shuffles, almost no barriers).
//   K3: single block merges 25x128 candidates each way -> exact global
//       top/bottom 128 (jax top_k tie semantics) -> BCE mean.
// ---------------------------------------------------------------------------

typedef unsigned long long ull;
typedef unsigned int uint;

#define CH 4096           // proposals per K2 block (8 warps x 512)
#define MAX_N 131072
#define MAX_CAND 4096

__device__ ull g_keys[MAX_N];
__device__ ull g_candT[MAX_CAND];   // keyT = (valbits<<32) | ~idx
__device__ ull g_candB[MAX_CAND];   // keyB = (valbits<<32) |  idx

// ======================= warp-level bitonic primitives =====================
// 128 elements per warp: element e = r*32 + lane, regs K[0..3].

__device__ __forceinline__ ull ce_shfl(ull v, int j, bool keepMin) {
    ull o = __shfl_xor_sync(0xFFFFFFFFu, v, j);
    bool take = keepMin ? (o < v) : (o > v);
    return take ? o : v;
}

__device__ __forceinline__ void ce_reg(ull& a, ull& b, bool up) {
    ull lo = a < b ? a : b;
    ull hi = a < b ? b : a;
    a = up ? lo : hi;
    b = up ? hi : lo;
}

// full ascending bitonic sort of the warp's 128 elements
__device__ __forceinline__ void warp_sort128(ull K[4]) {
    const int lane = threadIdx.x & 31;
    // k = 2..16: direction from lane
    #pragma unroll
    for (int k = 2; k <= 16; k <<= 1) {
        #pragma unroll
        for (int j = k >> 1; j >= 1; j >>= 1) {
            #pragma unroll
            for (int r = 0; r < 4; r++) {
                bool up = ((lane & k) == 0);
                bool lower = ((lane & j) == 0);
                K[r] = ce_shfl(K[r], j, up == lower);
            }
        }
    }
    // k = 32: direction from r&1
    #pragma unroll
    for (int j = 16; j >= 1; j >>= 1) {
        #pragma unroll
        for (int r = 0; r < 4; r++) {
            bool up = ((r & 1) == 0);
            bool lower = ((lane & j) == 0);
            K[r] = ce_shfl(K[r], j, up == lower);
        }
    }
    // k = 64: j=32 register stage, then shfl; direction from r&2
    ce_reg(K[0], K[1], true);
    ce_reg(K[2], K[3], false);
    #pragma unroll
    for (int j = 16; j >= 1; j >>= 1) {
        #pragma unroll
        for (int r = 0; r < 4; r++) {
            bool up = ((r & 2) == 0);
            bool lower = ((lane & j) == 0);
            K[r] = ce_shfl(K[r], j, up == lower);
        }
    }
    // k = 128: all ascending
    ce_reg(K[0], K[2], true); ce_reg(K[1], K[3], true);   // j=64
    ce_reg(K[0], K[1], true); ce_reg(K[2], K[3], true);   // j=32
    #pragma unroll
    for (int j = 16; j >= 1; j >>= 1)
        #pragma unroll
        for (int r = 0; r < 4; r++)
            K[r] = ce_shfl(K[r], j, (lane & j) == 0);
}

// sort an (already bitonic) sequence ascending
__device__ __forceinline__ void bitonic_merge_asc(ull A[4]) {
    const int lane = threadIdx.x & 31;
    ce_reg(A[0], A[2], true); ce_reg(A[1], A[3], true);
    ce_reg(A[0], A[1], true); ce_reg(A[2], A[3], true);
    #pragma unroll
    for (int j = 16; j >= 1; j >>= 1)
        #pragma unroll
        for (int r = 0; r < 4; r++)
            A[r] = ce_shfl(A[r], j, (lane & j) == 0);
}

// A asc, B asc -> A = the 128 smallest of A∪B, ascending
__device__ __forceinline__ void merge_keep_min(ull A[4], const ull B[4]) {
    ull Br[4];
    #pragma unroll
    for (int r = 0; r < 4; r++)
        Br[r] = __shfl_xor_sync(0xFFFFFFFFu, B[3 - r], 31);   // reverse of B
    #pragma unroll
    for (int r = 0; r < 4; r++)
        A[r] = A[r] < Br[r] ? A[r] : Br[r];
    bitonic_merge_asc(A);
}

// A asc, B asc -> A = the 128 largest of A∪B, ascending
__device__ __forceinline__ void merge_keep_max(ull A[4], const ull B[4]) {
    ull Br[4];
    #pragma unroll
    for (int r = 0; r < 4; r++)
        Br[r] = __shfl_xor_sync(0xFFFFFFFFu, B[3 - r], 31);
    #pragma unroll
    for (int r = 0; r < 4; r++)
        A[r] = A[r] > Br[r] ? A[r] : Br[r];
    bitonic_merge_asc(A);
}

// ============================ K1: IoU rowmax ===============================
__global__ void __launch_bounds__(256) iou_rowmax_kernel(
    const float4* __restrict__ props, const float4* __restrict__ gts,
    int n, int g)
{
    __shared__ float4 s_box[512];
    __shared__ float  s_area[512];

    const int t = threadIdx.x;
    const int i0 = blockIdx.x * 512 + t;
    const int i1 = i0 + 256;
    const bool v0 = i0 < n, v1 = i1 < n;

    float4 p0 = v0 ? props[i0] : make_float4(0.f, 0.f, 0.f, 0.f);
    float4 p1 = v1 ? props[i1] : make_float4(0.f, 0.f, 0.f, 0.f);
    float a0 = (p0.z - p0.x) * (p0.w - p0.y);
    float a1 = (p1.z - p1.x) * (p1.w - p1.y);

    float bI0 = 0.f, bU0 = 1.f, bI1 = 0.f, bU1 = 1.f;

    for (int t0 = 0; t0 < g; t0 += 512) {
        int cnt = min(512, g - t0);
        __syncthreads();
        for (int j = t; j < cnt; j += 256) {
            float4 b = gts[t0 + j];
            s_box[j]  = b;
            s_area[j] = (b.z - b.x) * (b.w - b.y);
        }
        __syncthreads();
        #pragma unroll 4
        for (int j = 0; j < cnt; j++) {
            float4 b = s_box[j];
            float  ga = s_area[j];
            // proposal 0
            {
                float lx = fmaxf(p0.x, b.x), ly = fmaxf(p0.y, b.y);
                float rx = fminf(p0.z, b.z), ry = fminf(p0.w, b.w);
                float w = fmaxf(rx - lx, 0.f), h = fmaxf(ry - ly, 0.f);
                float inter = w * h;
                float uni = (ga + a0) - inter;
                if (inter * bU0 > bI0 * uni) { bI0 = inter; bU0 = uni; }
            }
            // proposal 1
            {
                float lx = fmaxf(p1.x, b.x), ly = fmaxf(p1.y, b.y);
                float rx = fminf(p1.z, b.z), ry = fminf(p1.w, b.w);
                float w = fmaxf(rx - lx, 0.f), h = fmaxf(ry - ly, 0.f);
                float inter = w * h;
                float uni = (ga + a1) - inter;
                if (inter * bU1 > bI1 * uni) { bI1 = inter; bU1 = uni; }
            }
        }
    }

    if (v0) {
        float v = __fdiv_rn(bI0, bU0);
        g_keys[i0] = ((ull)__float_as_uint(v) << 32) | (uint)i0;
    }
    if (v1) {
        float v = __fdiv_rn(bI1, bU1);
        g_keys[i1] = ((ull)__float_as_uint(v) << 32) | (uint)i1;
    }
}

// =================== K2: per-chunk exact top/bottom 128 ====================
__global__ void __launch_bounds__(256) chunk_select_kernel(int n)
{
    __shared__ ull sLO[8][128];
    __shared__ ull sHI[8][128];

    const int w = threadIdx.x >> 5;
    const int lane = threadIdx.x & 31;
    const int base = blockIdx.x * CH + w * 512;

    ull LO[4], HI[4], T[4];

    // batch 0
    #pragma unroll
    for (int r = 0; r < 4; r++) {
        int gi = base + r * 32 + lane;
        bool vld = gi < n;
        ull k = vld ? g_keys[gi] : 0ull;
        LO[r] = vld ? k : ~0ull;
        HI[r] = vld ? (k ^ 0xFFFFFFFFull) : 0ull;
    }
    warp_sort128(LO);
    warp_sort128(HI);

    // batches 1..3
    #pragma unroll
    for (int b = 1; b < 4; b++) {
        #pragma unroll
        for (int r = 0; r < 4; r++) {
            int gi = base + b * 128 + r * 32 + lane;
            T[r] = (gi < n) ? g_keys[gi] : ~0ull;
        }
        warp_sort128(T);
        merge_keep_min(LO, T);
        #pragma unroll
        for (int r = 0; r < 4; r++) {
            int gi = base + b * 128 + r * 32 + lane;
            T[r] = (gi < n) ? (g_keys[gi] ^ 0xFFFFFFFFull) : 0ull;
        }
        warp_sort128(T);
        merge_keep_max(HI, T);
    }

    // cross-warp reduction: 8 -> 4 -> 2 -> 1
    #pragma unroll
    for (int half = 4; half >= 1; half >>= 1) {
        if (w < (half << 1)) {
            #pragma unroll
            for (int r = 0; r < 4; r++) {
                sLO[w][r * 32 + lane] = LO[r];
                sHI[w][r * 32 + lane] = HI[r];
            }
        }
        __syncthreads();
        if (w < half) {
            ull B[4];
            #pragma unroll
            for (int r = 0; r < 4; r++) B[r] = sLO[w + half][r * 32 + lane];
            merge_keep_min(LO, B);
            #pragma unroll
            for (int r = 0; r < 4; r++) B[r] = sHI[w + half][r * 32 + lane];
            merge_keep_max(HI, B);
        }
        __syncthreads();
    }

    if (w == 0) {
        #pragma unroll
        for (int r = 0; r < 4; r++) {
            g_candB[blockIdx.x * 128 + r * 32 + lane] = LO[r];
            g_candT[blockIdx.x * 128 + r * 32 + lane] = HI[r];
        }
    }
}

// ============ K3: global exact top/bottom 128 + BCE mean ===================
__global__ void __launch_bounds__(256) final_loss_kernel(
    int nc, const float* __restrict__ obj, float* __restrict__ out)
{
    __shared__ ull sLO[8][128];
    __shared__ ull sHI[8][128];

    const int w = threadIdx.x >> 5;
    const int lane = threadIdx.x & 31;
    const int per = (nc + 7) / 8;              // contiguous slice per warp
    const int base = w * per;

    ull LO[4], HI[4], T[4];

    #pragma unroll
    for (int r = 0; r < 4; r++) {
        int off = r * 32 + lane;
        bool vld = (off < per) && (base + off < nc);
        LO[r] = vld ? g_candB[base + off] : ~0ull;
        HI[r] = vld ? g_candT[base + off] : 0ull;
    }
    warp_sort128(LO);
    warp_sort128(HI);

    for (int b = 1; b * 128 < per; b++) {
        #pragma unroll
        for (int r = 0; r < 4; r++) {
            int off = b * 128 + r * 32 + lane;
            bool vld = (off < per) && (base + off < nc);
            T[r] = vld ? g_candB[base + off] : ~0ull;
        }
        warp_sort128(T);
        merge_keep_min(LO, T);
        #pragma unroll
        for (int r = 0; r < 4; r++) {
            int off = b * 128 + r * 32 + lane;
            bool vld = (off < per) && (base + off < nc);
            T[r] = vld ? g_candT[base + off] : 0ull;
        }
        warp_sort128(T);
        merge_keep_max(HI, T);
    }

    #pragma unroll
    for (int half = 4; half >= 1; half >>= 1) {
        if (w < (half << 1)) {
            #pragma unroll
            for (int r = 0; r < 4; r++) {
                sLO[w][r * 32 + lane] = LO[r];
                sHI[w][r * 32 + lane] = HI[r];
            }
        }
        __syncthreads();
        if (w < half) {
            ull B[4];
            #pragma unroll
            for (int r = 0; r < 4; r++) B[r] = sLO[w + half][r * 32 + lane];
            merge_keep_min(LO, B);
            #pragma unroll
            for (int r = 0; r < 4; r++) B[r] = sHI[w + half][r * 32 + lane];
            merge_keep_max(HI, B);
        }
        __syncthreads();
    }

    // warp 0 holds: LO = exact bottom-128 (keyB), HI = exact top-128 (keyT)
    if (w == 0) {
        float sum = 0.f;
        #pragma unroll
        for (int r = 0; r < 4; r++) {
            // top element: label = (val > 0.5)
            {
                float val = __uint_as_float((uint)(HI[r] >> 32));
                uint idx = ~(uint)(HI[r] & 0xFFFFFFFFull);
                float o = obj[idx];
                float p = fminf(fmaxf(o, 1e-7f), 1.0f - 1e-7f);
                sum += (val > 0.5f) ? logf(p) : log1pf(-p);
            }
            // bottom element: label = 0
            {
                uint idx = (uint)(LO[r] & 0xFFFFFFFFull);
                float o = obj[idx];
                float p = fminf(fmaxf(o, 1e-7f), 1.0f - 1e-7f);
                sum += log1pf(-p);
            }
        }
        #pragma unroll
        for (int off = 16; off >= 1; off >>= 1)
            sum += __shfl_xor_sync(0xFFFFFFFFu, sum, off);
        if (lane == 0) out[0] = -sum * (1.0f / 256.0f);
    }
}

// ---------------------------------------------------------------------------
extern "C" void kernel_launch(void* const* d_in, const int* in_sizes, int n_in,
                              void* d_out, int out_size)
{
    const float*  obj   = (const float*) d_in[0];
    const float4* props = (const float4*)d_in[1];
    const float4* gts   = (const float4*)d_in[2];
    int n = in_sizes[0];           // 100000
    int g = in_sizes[2] / 4;       // 512

    int nb1 = (n + 511) / 512;
    iou_rowmax_kernel<<<nb1, 256>>>(props, gts, n, g);

    int nb2 = (n + CH - 1) / CH;   // 25 chunks
    chunk_select_kernel<<<nb2, 256>>>(n);

    final_loss_kernel<<<1, 256>>>(nb2 * 128, obj, (float*)d_out);
}